// round 5
// baseline (speedup 1.0000x reference)
#include <cuda_runtime.h>

#define T_STEPS 4096
#define BATCH 64
#define IN_DIM 4
#define HID 256
#define OUT_DIM 2

// hidden-state history for the output head: [T, B, H] fp32 = 268 MB scratch
__device__ float g_hs[(size_t)T_STEPS * BATCH * HID];

__device__ __forceinline__ void fma2(unsigned long long &acc,
                                     unsigned long long a,
                                     unsigned long long b) {
    asm("fma.rn.f32x2 %0, %1, %2, %0;" : "+l"(acc) : "l"(a), "l"(b));
}

__device__ __forceinline__ float2 unpack2(unsigned long long v) {
    float2 f;
    asm("mov.b64 {%0, %1}, %2;" : "=f"(f.x), "=f"(f.y) : "l"(v));
    return f;
}

__device__ __forceinline__ unsigned int smem_u32(const void* p) {
    unsigned int a;
    asm("{ .reg .u64 t; cvta.to.shared.u64 t, %1; cvt.u32.u64 %0, t; }"
        : "=r"(a) : "l"(p));
    return a;
}

__device__ __forceinline__ unsigned int mapa_peer(unsigned int laddr,
                                                  unsigned int peer) {
    unsigned int r;
    asm("mapa.shared::cluster.u32 %0, %1, %2;" : "=r"(r) : "r"(laddr), "r"(peer));
    return r;
}

// 128-MAC dot product: 64 packed f32x2 FMAs against broadcast LDS.128 reads
__device__ __forceinline__ float dot128(const unsigned long long* __restrict__ wh,
                                        const float* __restrict__ hsrc) {
    const ulonglong2* h2 = (const ulonglong2*)hsrc;
    unsigned long long a0 = 0ull, a1 = 0ull, a2 = 0ull, a3 = 0ull;
#pragma unroll
    for (int m = 0; m < 32; m += 2) {
        ulonglong2 hm0 = h2[m];
        fma2(a0, wh[2 * m],     hm0.x);
        fma2(a1, wh[2 * m + 1], hm0.y);
        ulonglong2 hm1 = h2[m + 1];
        fma2(a2, wh[2 * m + 2], hm1.x);
        fma2(a3, wh[2 * m + 3], hm1.y);
    }
    float2 f0 = unpack2(a0), f1 = unpack2(a1);
    float2 f2 = unpack2(a2), f3 = unpack2(a3);
    return ((f0.x + f0.y) + (f1.x + f1.y)) + ((f2.x + f2.y) + (f3.x + f3.y));
}

// ---------------------------------------------------------------------------
// Recurrence, K-split, TWO batches per 2-CTA cluster (comm latency of one
// batch hides under the other batch's FMA work). Cluster c = batches
// (2c, 2c+1). CTA rank r owns k-range [128r,+128) of h and finalizes outputs
// j in the same range, for BOTH batches with the SAME register-resident
// weights Wh[j'][k-range] (64 f32x2 regs/thread).
//   warps 4..7 (hi-wid, issue priority): peer-destined partials: compute A,
//       st.shared::cluster + warp release-arrive; then B likewise. Transit
//       overlaps everything below.
//   warps 0..3: local partials for A then B (+xi+bias), then wait A / tanh /
//       store, wait B / tanh / store.
// One __syncthreads per iteration; no cluster barrier in the loop.
// ---------------------------------------------------------------------------
__global__ void __launch_bounds__(256, 1) __cluster_dims__(2, 1, 1)
elman_recurrence(const float* __restrict__ input,
                 const float* __restrict__ Wi,
                 const float* __restrict__ bi,
                 const float* __restrict__ Wh,
                 const float* __restrict__ bh) {
    __shared__ __align__(16) float hA[2][128], hB[2][128];  // local h halves
    __shared__ __align__(16) float pA[2][128], pB[2][128];  // incoming partials
    __shared__ __align__(8) unsigned long long mbA[2], mbB[2];

    const int tid  = threadIdx.x;
    const int rank = blockIdx.x & 1;
    const int c    = blockIdx.x >> 1;
    const int bA   = 2 * c;
    const int bB   = 2 * c + 1;
    const unsigned int peer = rank ^ 1;
    const bool is_local = (tid < 128);          // warps 0-3 = finalizers
    const int  li = tid & 127;

    const int j_out = (is_local ? 128 * rank : 128 * (1 - rank)) + li;

    // --- loop-invariant weights Wh[j_out][128*rank .. +128) in registers ---
    unsigned long long wh[64];
    {
        const ulonglong2* wsrc =
            (const ulonglong2*)(Wh + (size_t)j_out * HID + rank * 128);
#pragma unroll
        for (int m = 0; m < 32; ++m) {
            ulonglong2 v = __ldg(wsrc + m);
            wh[2 * m]     = v.x;
            wh[2 * m + 1] = v.y;
        }
    }

    // --- finalizer constants (same Wi row / bias for both batches) ---
    float4 wi4 = make_float4(0.f, 0.f, 0.f, 0.f);
    float  cb  = 0.f;
    if (is_local) {
        wi4 = __ldg((const float4*)(Wi + (size_t)j_out * IN_DIM));
        cb  = __ldg(bi + j_out) + __ldg(bh + j_out);
    }

    // --- remote addresses (producers): peer pbuf slots + peer mbars ---
    unsigned int r_pA0 = 0, r_pA1 = 0, r_pB0 = 0, r_pB1 = 0;
    unsigned int r_mA0 = 0, r_mA1 = 0, r_mB0 = 0, r_mB1 = 0;
    if (!is_local) {
        r_pA0 = mapa_peer(smem_u32(&pA[0][li]), peer);
        r_pA1 = mapa_peer(smem_u32(&pA[1][li]), peer);
        r_pB0 = mapa_peer(smem_u32(&pB[0][li]), peer);
        r_pB1 = mapa_peer(smem_u32(&pB[1][li]), peer);
        r_mA0 = mapa_peer(smem_u32(&mbA[0]), peer);
        r_mA1 = mapa_peer(smem_u32(&mbA[1]), peer);
        r_mB0 = mapa_peer(smem_u32(&mbB[0]), peer);
        r_mB1 = mapa_peer(smem_u32(&mbB[1]), peer);
    }
    const unsigned int l_mA0 = smem_u32(&mbA[0]);
    const unsigned int l_mA1 = smem_u32(&mbA[1]);
    const unsigned int l_mB0 = smem_u32(&mbB[0]);
    const unsigned int l_mB1 = smem_u32(&mbB[1]);

    // --- init: mbarriers (4 producer-warp arrives each), h0 = 0 ---
    if (tid == 0) {
        asm volatile("mbarrier.init.shared.b64 [%0], %1;" :: "r"(l_mA0), "r"(4u) : "memory");
        asm volatile("mbarrier.init.shared.b64 [%0], %1;" :: "r"(l_mA1), "r"(4u) : "memory");
        asm volatile("mbarrier.init.shared.b64 [%0], %1;" :: "r"(l_mB0), "r"(4u) : "memory");
        asm volatile("mbarrier.init.shared.b64 [%0], %1;" :: "r"(l_mB1), "r"(4u) : "memory");
    }
    if (is_local) { hA[0][li] = 0.f; hB[0][li] = 0.f; }
    __syncthreads();
    asm volatile("barrier.cluster.arrive.aligned;" ::: "memory");
    asm volatile("barrier.cluster.wait.aligned;" ::: "memory");

    // prefetch xi for t=0 (finalizers)
    float4 xinA = make_float4(0.f, 0.f, 0.f, 0.f);
    float4 xinB = xinA;
    if (is_local) {
        xinA = __ldg((const float4*)(input + (size_t)bA * IN_DIM));
        xinB = __ldg((const float4*)(input + (size_t)bB * IN_DIM));
    }

    float* hsA = g_hs + (size_t)bA * HID + (size_t)j_out;
    float* hsB = g_hs + (size_t)bB * HID + (size_t)j_out;

    for (int t = 0; t < T_STEPS; ++t) {
        const int cur = t & 1;
        const unsigned int par = (t >> 1) & 1;

        if (!is_local) {
            // ---- producers: ship A first (starts transit early), then B ----
            float partA = dot128(wh, hA[cur]);
            asm volatile("st.shared::cluster.f32 [%0], %1;"
                         :: "r"(cur ? r_pA1 : r_pA0), "f"(partA) : "memory");
            __syncwarp();
            if ((tid & 31) == 0)
                asm volatile("mbarrier.arrive.release.cluster.shared::cluster.b64 _, [%0];"
                             :: "r"(cur ? r_mA1 : r_mA0) : "memory");

            float partB = dot128(wh, hB[cur]);
            asm volatile("st.shared::cluster.f32 [%0], %1;"
                         :: "r"(cur ? r_pB1 : r_pB0), "f"(partB) : "memory");
            __syncwarp();
            if ((tid & 31) == 0)
                asm volatile("mbarrier.arrive.release.cluster.shared::cluster.b64 _, [%0];"
                             :: "r"(cur ? r_mB1 : r_mB0) : "memory");
        } else {
            // ---- finalizers: both local dot products BEFORE any wait ----
            float4 xnA = xinA, xnB = xinB;
            if (t + 1 < T_STEPS) {
                xnA = __ldg((const float4*)(input +
                            ((size_t)(t + 1) * BATCH + bA) * IN_DIM));
                xnB = __ldg((const float4*)(input +
                            ((size_t)(t + 1) * BATCH + bB) * IN_DIM));
            }

            float preA = dot128(wh, hA[cur]) + xinA.x * wi4.x + xinA.y * wi4.y +
                         xinA.z * wi4.z + xinA.w * wi4.w + cb;
            float preB = dot128(wh, hB[cur]) + xinB.x * wi4.x + xinB.y * wi4.y +
                         xinB.z * wi4.z + xinB.w * wi4.w + cb;

            // wait A (peer release -> cluster-scope acquire), finalize A
            asm volatile(
                "{\n\t.reg .pred P;\n\t"
                "WA_%=:\n\t"
                "mbarrier.try_wait.parity.acquire.cluster.shared::cta.b64 P, [%0], %1, 0x989680;\n\t"
                "@!P bra WA_%=;\n\t}"
                :: "r"(cur ? l_mA1 : l_mA0), "r"(par) : "memory");
            float hnA = tanhf(preA + pA[cur][li]);
            hA[cur ^ 1][li] = hnA;
            hsA[(size_t)t * (BATCH * HID)] = hnA;

            // wait B, finalize B
            asm volatile(
                "{\n\t.reg .pred P;\n\t"
                "WB_%=:\n\t"
                "mbarrier.try_wait.parity.acquire.cluster.shared::cta.b64 P, [%0], %1, 0x989680;\n\t"
                "@!P bra WB_%=;\n\t}"
                :: "r"(cur ? l_mB1 : l_mB0), "r"(par) : "memory");
            float hnB = tanhf(preB + pB[cur][li]);
            hB[cur ^ 1][li] = hnB;
            hsB[(size_t)t * (BATCH * HID)] = hnB;

            xinA = xnA;
            xinB = xnB;
        }

        // local visibility of hA/hB[nxt] for all 8 warps
        __syncthreads();
    }

    // keep cluster alive until last in-flight remote stores/arrives land
    asm volatile("barrier.cluster.arrive.aligned;" ::: "memory");
    asm volatile("barrier.cluster.wait.aligned;" ::: "memory");
}

// ---------------------------------------------------------------------------
// Output head: out[t,b,:] = tanh(hs[t,b,:] @ Wf^T + bf). One warp per row,
// grid-stride; memory-bound (streams 268 MB of hs).
// ---------------------------------------------------------------------------
__global__ void __launch_bounds__(256)
elman_head(const float* __restrict__ Wf,
           const float* __restrict__ bf,
           float* __restrict__ out) {
    const int lane   = threadIdx.x & 31;
    const int gwarp  = (blockIdx.x * blockDim.x + threadIdx.x) >> 5;
    const int nwarps = (gridDim.x * blockDim.x) >> 5;

    const float bf0 = __ldg(bf + 0);
    const float bf1 = __ldg(bf + 1);

    const float4* wf0p = (const float4*)(Wf) + lane * 2;
    const float4* wf1p = (const float4*)(Wf + HID) + lane * 2;
    const float4 w00 = __ldg(wf0p), w01 = __ldg(wf0p + 1);
    const float4 w10 = __ldg(wf1p), w11 = __ldg(wf1p + 1);

    const int nrows = T_STEPS * BATCH;
    for (int row = gwarp; row < nrows; row += nwarps) {
        const float4* h = (const float4*)(g_hs + (size_t)row * HID) + lane * 2;
        float4 h0 = h[0], h1 = h[1];
        float s0 = h0.x * w00.x + h0.y * w00.y + h0.z * w00.z + h0.w * w00.w +
                   h1.x * w01.x + h1.y * w01.y + h1.z * w01.z + h1.w * w01.w;
        float s1 = h0.x * w10.x + h0.y * w10.y + h0.z * w10.z + h0.w * w10.w +
                   h1.x * w11.x + h1.y * w11.y + h1.z * w11.z + h1.w * w11.w;
#pragma unroll
        for (int o = 16; o; o >>= 1) {
            s0 += __shfl_xor_sync(0xffffffffu, s0, o);
            s1 += __shfl_xor_sync(0xffffffffu, s1, o);
        }
        if (lane == 0) {
            out[(size_t)row * OUT_DIM + 0] = tanhf(s0 + bf0);
            out[(size_t)row * OUT_DIM + 1] = tanhf(s1 + bf1);
        }
    }
}

extern "C" void kernel_launch(void* const* d_in, const int* in_sizes, int n_in,
                              void* d_out, int out_size) {
    // metadata order: input, target, Wi, bi, Wh, bh, Wf, bf
    const float* input = (const float*)d_in[0];
    const float* Wi = (const float*)d_in[2];
    const float* bi = (const float*)d_in[3];
    const float* Wh = (const float*)d_in[4];
    const float* bh = (const float*)d_in[5];
    const float* Wf = (const float*)d_in[6];
    const float* bf = (const float*)d_in[7];
    float* out = (float*)d_out;

    // 32 clusters x 2 CTAs, 2 batches per cluster
    elman_recurrence<<<BATCH, 256>>>(input, Wi, bi, Wh, bh);
    elman_head<<<2048, 256>>>(Wf, bf, out);
}